// round 2
// baseline (speedup 1.0000x reference)
#include <cuda_runtime.h>
#include <cuda_bf16.h>
#include <cstddef>

#define NN 50000
#define EE 800000
#define DD 128
#define GG 4
#define BN_EPS 1e-5f

// ---------------- static scratch (no allocations allowed) ----------------
__device__ float g_deg[NN];
__device__ float g_dinv[NN];
__device__ float g_norm[EE];
__device__ float g_xa[(size_t)NN * DD];   // P @ x   (shared across all g)
__device__ float g_z1[(size_t)NN * DD];   // layer-1 activation (per g, reused)
__device__ float g_h2[(size_t)NN * DD];   // z1 @ W2
__device__ float g_t2[(size_t)NN * DD];   // P @ h2
__device__ float g_mix[(size_t)NN * GG];
__device__ float g_sum[DD];
__device__ float g_sumsq[DD];

// ---------------- small helpers ----------------
__device__ __forceinline__ void red_add_v4(float* addr, float4 v) {
#if defined(__CUDA_ARCH__) && (__CUDA_ARCH__ >= 900)
    asm volatile("red.global.add.v4.f32 [%0], {%1, %2, %3, %4};"
                 :: "l"(addr), "f"(v.x), "f"(v.y), "f"(v.z), "f"(v.w)
                 : "memory");
#else
    atomicAdd(addr + 0, v.x);
    atomicAdd(addr + 1, v.y);
    atomicAdd(addr + 2, v.z);
    atomicAdd(addr + 3, v.w);
#endif
}

// ---------------- setup kernels ----------------
__global__ void k_init_deg(float* deg) {
    int i = blockIdx.x * blockDim.x + threadIdx.x;
    if (i < NN) deg[i] = 1.0f;  // self-loop contribution
}

__global__ void k_count_deg(const int* __restrict__ col, float* deg) {
    int e = blockIdx.x * blockDim.x + threadIdx.x;
    if (e >= EE) return;
    int c = col[e];
    if ((unsigned)c < (unsigned)NN) atomicAdd(&deg[c], 1.0f);
}

__global__ void k_dinv(const float* __restrict__ deg, float* dinv) {
    int i = blockIdx.x * blockDim.x + threadIdx.x;
    if (i < NN) dinv[i] = rsqrtf(deg[i]);   // deg >= 1 always (self-loop)
}

__global__ void k_edge_norm(const int* __restrict__ row,
                            const int* __restrict__ col,
                            const float* __restrict__ dinv,
                            float* __restrict__ norm) {
    int e = blockIdx.x * blockDim.x + threadIdx.x;
    if (e >= EE) return;
    int r = row[e];
    int c = col[e];
    float v = 0.0f;
    if ((unsigned)r < (unsigned)NN && (unsigned)c < (unsigned)NN)
        v = dinv[r] * dinv[c];
    norm[e] = v;
}

__global__ void k_mix_softmax(const float* __restrict__ me, float* __restrict__ mix) {
    int n = blockIdx.x * blockDim.x + threadIdx.x;
    if (n >= NN) return;
    float m0 = me[n * 4 + 0], m1 = me[n * 4 + 1], m2 = me[n * 4 + 2], m3 = me[n * 4 + 3];
    float mx = fmaxf(fmaxf(m0, m1), fmaxf(m2, m3));
    float e0 = expf(m0 - mx), e1 = expf(m1 - mx), e2 = expf(m2 - mx), e3 = expf(m3 - mx);
    float inv = 1.0f / (e0 + e1 + e2 + e3);
    mix[n * 4 + 0] = e0 * inv;
    mix[n * 4 + 1] = e1 * inv;
    mix[n * 4 + 2] = e2 * inv;
    mix[n * 4 + 3] = e3 * inv;
}

// ---------------- propagate: init with self-loop, then edge scatter ----------------
__global__ void k_selfloop(const float4* __restrict__ src,
                           const float* __restrict__ dinv,
                           float4* __restrict__ dst) {
    int idx = blockIdx.x * blockDim.x + threadIdx.x;   // NN*32 v4 chunks
    if (idx >= NN * 32) return;
    int n = idx >> 5;
    float w = dinv[n] * dinv[n];
    float4 v = src[idx];
    v.x *= w; v.y *= w; v.z *= w; v.w *= w;
    dst[idx] = v;
}

__global__ void k_scatter(const float4* __restrict__ src,
                          float* __restrict__ dst,
                          const int* __restrict__ row,
                          const int* __restrict__ col,
                          const float* __restrict__ norm) {
    int gid = blockIdx.x * blockDim.x + threadIdx.x;   // EE*32 v4 tasks
    if (gid >= EE * 32) return;
    int e = gid >> 5;
    int c = gid & 31;
    int r = row[e];
    int t = col[e];
    if ((unsigned)r >= (unsigned)NN || (unsigned)t >= (unsigned)NN) return;
    float w = norm[e];
    float4 v = src[(size_t)r * 32 + c];
    v.x *= w; v.y *= w; v.z *= w; v.w *= w;
    red_add_v4(dst + (size_t)t * DD + c * 4, v);
}

// ---------------- GEMM: C[M,128] = A[M,128] @ W[128,128] (fp32 SIMT) ----------------
#define GEMM_SMEM ((128 * 129 + 128 * 128) * 4)

__global__ void k_gemm128(const float* __restrict__ A,
                          const float* __restrict__ W,
                          float* __restrict__ C, int M) {
    extern __shared__ float sm[];
    float (*As)[129] = (float (*)[129])sm;                 // [m][k], padded
    float (*Ws)[128] = (float (*)[128])(sm + 128 * 129);   // [k][c]
    int tid  = threadIdx.x;            // 256 threads
    int row0 = blockIdx.x * 128;

    // load A tile (guard M tail)
    for (int i = tid; i < 128 * 32; i += 256) {
        int m  = i >> 5;
        int k4 = (i & 31) << 2;
        int r  = row0 + m;
        float4 v = make_float4(0.f, 0.f, 0.f, 0.f);
        if (r < M) v = *(const float4*)(A + (size_t)r * 128 + k4);
        As[m][k4 + 0] = v.x; As[m][k4 + 1] = v.y; As[m][k4 + 2] = v.z; As[m][k4 + 3] = v.w;
    }
    // load W tile (always full)
    for (int i = tid; i < 128 * 32; i += 256) {
        int k  = i >> 5;
        int c4 = (i & 31) << 2;
        *(float4*)&Ws[k][c4] = *(const float4*)(W + (size_t)k * 128 + c4);
    }
    __syncthreads();

    int tx = tid & 15, ty = tid >> 4;
    int mBase = ty * 8, cBase = tx * 8;
    float acc[8][8];
    #pragma unroll
    for (int i = 0; i < 8; ++i)
        #pragma unroll
        for (int j = 0; j < 8; ++j) acc[i][j] = 0.f;

    #pragma unroll 8
    for (int k = 0; k < 128; ++k) {
        float a[8];
        #pragma unroll
        for (int i = 0; i < 8; ++i) a[i] = As[mBase + i][k];
        float4 b0 = *(const float4*)&Ws[k][cBase];
        float4 b1 = *(const float4*)&Ws[k][cBase + 4];
        float b[8] = {b0.x, b0.y, b0.z, b0.w, b1.x, b1.y, b1.z, b1.w};
        #pragma unroll
        for (int i = 0; i < 8; ++i)
            #pragma unroll
            for (int j = 0; j < 8; ++j)
                acc[i][j] += a[i] * b[j];
    }

    #pragma unroll
    for (int i = 0; i < 8; ++i) {
        int r = row0 + mBase + i;
        if (r < M) {
            *(float4*)(C + (size_t)r * 128 + cBase)     = make_float4(acc[i][0], acc[i][1], acc[i][2], acc[i][3]);
            *(float4*)(C + (size_t)r * 128 + cBase + 4) = make_float4(acc[i][4], acc[i][5], acc[i][6], acc[i][7]);
        }
    }
}

// ---------------- BatchNorm statistics ----------------
__global__ void k_zero_stats(float* sum, float* sumsq) {
    int t = threadIdx.x;
    if (t < DD) { sum[t] = 0.f; sumsq[t] = 0.f; }
}

__global__ void k_bn_stats(const float* __restrict__ z,
                           float* __restrict__ sum, float* __restrict__ sumsq) {
    int c  = threadIdx.x;                 // 128 threads = 128 columns
    int r0 = blockIdx.x * 128;
    int r1 = min(r0 + 128, NN);
    float s = 0.f, s2 = 0.f;
    for (int r = r0; r < r1; ++r) {
        float v = z[(size_t)r * DD + c];
        s  += v;
        s2 += v * v;
    }
    atomicAdd(&sum[c], s);
    atomicAdd(&sumsq[c], s2);
}

// BN apply + PReLU, in place
__global__ void k_bn_prelu(float* __restrict__ z,
                           const float* __restrict__ sum, const float* __restrict__ sumsq,
                           const float* __restrict__ gamma, const float* __restrict__ beta,
                           const float* __restrict__ alpha_p) {
    int idx = blockIdx.x * blockDim.x + threadIdx.x;
    if (idx >= NN * DD) return;
    int c = idx & 127;
    const float invN = 1.0f / (float)NN;
    float mu  = sum[c] * invN;
    float var = sumsq[c] * invN - mu * mu;
    float rs  = rsqrtf(var + BN_EPS);
    float v   = (z[idx] - mu) * rs * gamma[c] + beta[c];
    float a   = *alpha_p;
    z[idx] = (v > 0.f) ? v : a * v;
}

// BN apply + PReLU + mixture accumulate into output
__global__ void k_bn_prelu_mix(const float* __restrict__ t,
                               const float* __restrict__ sum, const float* __restrict__ sumsq,
                               const float* __restrict__ gamma, const float* __restrict__ beta,
                               const float* __restrict__ alpha_p,
                               const float* __restrict__ mix, int g,
                               float* __restrict__ out, int first) {
    int idx = blockIdx.x * blockDim.x + threadIdx.x;
    if (idx >= NN * DD) return;
    int c = idx & 127;
    const float invN = 1.0f / (float)NN;
    float mu  = sum[c] * invN;
    float var = sumsq[c] * invN - mu * mu;
    float rs  = rsqrtf(var + BN_EPS);
    float v   = (t[idx] - mu) * rs * gamma[c] + beta[c];
    float a   = *alpha_p;
    v = (v > 0.f) ? v : a * v;
    float m = mix[(size_t)(idx >> 7) * GG + g];
    if (first) out[idx] = m * v;
    else       out[idx] += m * v;
}

// ---------------- launch ----------------
extern "C" void kernel_launch(void* const* d_in, const int* in_sizes, int n_in,
                              void* d_out, int out_size) {
    const float* x      = (const float*)d_in[0];
    const int*   ei     = (const int*)d_in[1];        // [2, E] int32 (JAX x64 off)
    const float* W1     = (const float*)d_in[2];      // [G,128,128]
    const float* W2     = (const float*)d_in[4];      // [G,128,128]
    const float* gamma1 = (const float*)d_in[6];
    const float* beta1  = (const float*)d_in[7];
    const float* gamma2 = (const float*)d_in[8];
    const float* beta2  = (const float*)d_in[9];
    const float* alpha  = (const float*)d_in[10];
    const float* mixe   = (const float*)d_in[11];
    float*       out    = (float*)d_out;

    void* p;
    cudaGetSymbolAddress(&p, g_deg);   float* deg  = (float*)p;
    cudaGetSymbolAddress(&p, g_dinv);  float* dinv = (float*)p;
    cudaGetSymbolAddress(&p, g_norm);  float* norm = (float*)p;
    cudaGetSymbolAddress(&p, g_xa);    float* xa   = (float*)p;
    cudaGetSymbolAddress(&p, g_z1);    float* z1   = (float*)p;
    cudaGetSymbolAddress(&p, g_h2);    float* h2   = (float*)p;
    cudaGetSymbolAddress(&p, g_t2);    float* t2   = (float*)p;
    cudaGetSymbolAddress(&p, g_mix);   float* mix  = (float*)p;
    cudaGetSymbolAddress(&p, g_sum);   float* sum  = (float*)p;
    cudaGetSymbolAddress(&p, g_sumsq); float* sumsq= (float*)p;

    const int* row = ei;        // source nodes
    const int* col = ei + EE;   // target nodes

    const int T = 256;
    const int gN   = (NN + T - 1) / T;
    const int gE   = (EE + T - 1) / T;
    const int gN32 = (NN * 32 + T - 1) / T;
    const int gE32 = (EE * 32 + T - 1) / T;
    const int gND  = (NN * DD + T - 1) / T;
    const int gRow = (NN + 127) / 128;

    cudaFuncSetAttribute(k_gemm128, cudaFuncAttributeMaxDynamicSharedMemorySize, GEMM_SMEM);

    // graph normalization (recomputed every call: deterministic)
    k_init_deg<<<gN, T>>>(deg);
    k_count_deg<<<gE, T>>>(col, deg);
    k_dinv<<<gN, T>>>(deg, dinv);
    k_edge_norm<<<gE, T>>>(row, col, dinv, norm);
    k_mix_softmax<<<gN, T>>>(mixe, mix);

    // shared layer-1 propagate:  xa = P @ x   (P commutes with the @W1 GEMM)
    k_selfloop<<<gN32, T>>>((const float4*)x, dinv, (float4*)xa);
    k_scatter<<<gE32, T>>>((const float4*)x, xa, row, col, norm);

    for (int g = 0; g < GG; ++g) {
        // layer 1: z1 = (P x) @ W1[g]   (b1 cancels inside BN)
        k_gemm128<<<gRow, T, GEMM_SMEM>>>(xa, W1 + (size_t)g * DD * DD, z1, NN);
        k_zero_stats<<<1, 128>>>(sum, sumsq);
        k_bn_stats<<<gRow, 128>>>(z1, sum, sumsq);
        k_bn_prelu<<<gND, T>>>(z1, sum, sumsq, gamma1 + g * DD, beta1 + g * DD, alpha);

        // layer 2: t2 = P (z1 @ W2[g])   (b2 cancels inside BN)
        k_gemm128<<<gRow, T, GEMM_SMEM>>>(z1, W2 + (size_t)g * DD * DD, h2, NN);
        k_selfloop<<<gN32, T>>>((const float4*)h2, dinv, (float4*)t2);
        k_scatter<<<gE32, T>>>((const float4*)h2, t2, row, col, norm);
        k_zero_stats<<<1, 128>>>(sum, sumsq);
        k_bn_stats<<<gRow, 128>>>(t2, sum, sumsq);
        k_bn_prelu_mix<<<gND, T>>>(t2, sum, sumsq, gamma2 + g * DD, beta2 + g * DD,
                                   alpha, mix, g, out, g == 0 ? 1 : 0);
    }
}

// round 4
// speedup vs baseline: 2.0721x; 2.0721x over previous
#include <cuda_runtime.h>
#include <cuda_bf16.h>
#include <cstdint>
#include <cstddef>

#define NN 50000
#define EE 800000
#define DD 128
#define GG 4
#define BN_EPS 1e-5f

// ---------------- static scratch (no allocations allowed) ----------------
__device__ int   g_cnt[NN + 1];
__device__ int   g_rowptr[NN + 1];
__device__ int   g_cursor[NN];
__device__ int   g_bsum[128];
__device__ int   g_esrc[EE];
__device__ float g_enorm[EE];
__device__ float g_dinv[NN];
__device__ float g_xa[(size_t)NN * DD];
__device__ float g_z1[(size_t)NN * DD];
__device__ float g_h2[(size_t)NN * DD];
__device__ float g_t2[(size_t)NN * DD];
__device__ float g_mix[(size_t)NN * GG];
__device__ float g_sum[DD];
__device__ float g_sumsq[DD];
__device__ __nv_bfloat16 g_w1h[(size_t)GG * DD * DD];
__device__ __nv_bfloat16 g_w1l[(size_t)GG * DD * DD];
__device__ __nv_bfloat16 g_w2h[(size_t)GG * DD * DD];
__device__ __nv_bfloat16 g_w2l[(size_t)GG * DD * DD];

// ---------------- setup: degree, CSR build, softmax, weight split ----------------
__global__ void k_zero_cnt(int* cnt) {
    int i = blockIdx.x * blockDim.x + threadIdx.x;
    if (i <= NN) cnt[i] = 0;
}
__global__ void k_hist(const int* __restrict__ col, int* cnt) {
    int e = blockIdx.x * blockDim.x + threadIdx.x;
    if (e >= EE) return;
    int c = col[e];
    if ((unsigned)c < (unsigned)NN) atomicAdd(&cnt[c], 1);
}
__global__ void k_dinv(const int* __restrict__ cnt, float* dinv) {
    int i = blockIdx.x * blockDim.x + threadIdx.x;
    if (i < NN) dinv[i] = rsqrtf((float)cnt[i] + 1.0f);  // +1 self-loop
}
// exclusive scan of cnt[0..NN] -> rowptr, 3 phases
__global__ void k_scan1(const int* __restrict__ cnt, int* __restrict__ rowptr, int* __restrict__ bsum) {
    __shared__ int s[512];
    int tid = threadIdx.x;
    int i = blockIdx.x * 512 + tid;
    int v = (i <= NN) ? cnt[i] : 0;
    s[tid] = v;
    __syncthreads();
    #pragma unroll
    for (int off = 1; off < 512; off <<= 1) {
        int t = (tid >= off) ? s[tid - off] : 0;
        __syncthreads();
        s[tid] += t;
        __syncthreads();
    }
    if (i <= NN) rowptr[i] = s[tid] - v;   // exclusive within block
    if (tid == 511) bsum[blockIdx.x] = s[511];
}
__global__ void k_scan2(int* bsum, int nb) {
    __shared__ int s[128];
    int tid = threadIdx.x;
    int v = (tid < nb) ? bsum[tid] : 0;
    s[tid] = v;
    __syncthreads();
    #pragma unroll
    for (int off = 1; off < 128; off <<= 1) {
        int t = (tid >= off) ? s[tid - off] : 0;
        __syncthreads();
        s[tid] += t;
        __syncthreads();
    }
    if (tid < nb) bsum[tid] = s[tid] - v;  // exclusive block offsets
}
__global__ void k_scan3(int* __restrict__ rowptr, const int* __restrict__ bsum, int* __restrict__ cursor) {
    int i = blockIdx.x * 512 + threadIdx.x;
    if (i <= NN) {
        int r = rowptr[i] + bsum[blockIdx.x];
        rowptr[i] = r;
        if (i < NN) cursor[i] = r;
    }
}
__global__ void k_place(const int* __restrict__ row, const int* __restrict__ col,
                        const float* __restrict__ dinv,
                        int* __restrict__ cursor, int* __restrict__ esrc, float* __restrict__ enorm) {
    int e = blockIdx.x * blockDim.x + threadIdx.x;
    if (e >= EE) return;
    int r = row[e], c = col[e];
    if ((unsigned)r >= (unsigned)NN || (unsigned)c >= (unsigned)NN) return;
    int pos = atomicAdd(&cursor[c], 1);
    esrc[pos] = r;
    enorm[pos] = dinv[r] * dinv[c];
}
__global__ void k_mix_softmax(const float* __restrict__ me, float* __restrict__ mix) {
    int n = blockIdx.x * blockDim.x + threadIdx.x;
    if (n >= NN) return;
    float m0 = me[n*4+0], m1 = me[n*4+1], m2 = me[n*4+2], m3 = me[n*4+3];
    float mx = fmaxf(fmaxf(m0, m1), fmaxf(m2, m3));
    float e0 = expf(m0-mx), e1 = expf(m1-mx), e2 = expf(m2-mx), e3 = expf(m3-mx);
    float inv = 1.0f / (e0 + e1 + e2 + e3);
    mix[n*4+0] = e0*inv; mix[n*4+1] = e1*inv; mix[n*4+2] = e2*inv; mix[n*4+3] = e3*inv;
}
// split W into bf16 hi/lo, transposed to [g][n][k]
__global__ void k_split_w(const float* __restrict__ W,
                          __nv_bfloat16* __restrict__ Wh, __nv_bfloat16* __restrict__ Wl) {
    int idx = blockIdx.x * blockDim.x + threadIdx.x;
    if (idx >= GG * DD * DD) return;
    int g = idx >> 14, rem = idx & 16383, n = rem >> 7, k = rem & 127;
    float w = W[(g << 14) + (k << 7) + n];
    __nv_bfloat16 h = __float2bfloat16(w);
    Wh[idx] = h;
    Wl[idx] = __float2bfloat16(w - __bfloat162float(h));
}

// ---------------- propagate: CSR gather, warp per node, self-loop fused ----------------
__global__ void __launch_bounds__(256) k_gather(
    const float4* __restrict__ src, float4* __restrict__ dst,
    const int* __restrict__ rowptr, const int* __restrict__ esrc,
    const float* __restrict__ enorm, const float* __restrict__ dinv)
{
    int wid = threadIdx.x >> 5, lane = threadIdx.x & 31;
    int n = blockIdx.x * 8 + wid;
    if (n >= NN) return;
    float dw = dinv[n];
    float w0 = dw * dw;
    float4 a = src[(size_t)n * 32 + lane];
    float4 acc = make_float4(a.x * w0, a.y * w0, a.z * w0, a.w * w0);
    int j0 = rowptr[n], j1 = rowptr[n + 1];
    for (int j = j0; j < j1; ++j) {
        int s = esrc[j];
        float w = enorm[j];
        float4 v = src[(size_t)s * 32 + lane];
        acc.x += w * v.x; acc.y += w * v.y; acc.z += w * v.z; acc.w += w * v.w;
    }
    dst[(size_t)n * 32 + lane] = acc;
}

// ---------------- GEMM: C[M,128] = A[M,128] @ W^T via mma.sync bf16 3-term split ----------------
// smem: WH | WL | AH | AL, each 128 rows x 136 bf16 (272B row stride)
#define TROW 272
#define SM_WH 0
#define SM_WL (SM_WH + 128 * TROW)
#define SM_AH (SM_WL + 128 * TROW)
#define SM_AL (SM_AH + 128 * TROW)
#define GT_SMEM (SM_AL + 128 * TROW)

__device__ __forceinline__ void mma_bf16(float* d, const uint32_t* a, const uint32_t* b) {
    asm volatile(
        "mma.sync.aligned.m16n8k16.row.col.f32.bf16.bf16.f32 "
        "{%0,%1,%2,%3}, {%4,%5,%6,%7}, {%8,%9}, {%0,%1,%2,%3};"
        : "+f"(d[0]), "+f"(d[1]), "+f"(d[2]), "+f"(d[3])
        : "r"(a[0]), "r"(a[1]), "r"(a[2]), "r"(a[3]), "r"(b[0]), "r"(b[1]));
}
__device__ __forceinline__ uint32_t pack_bf2(float x, float y) {
    __nv_bfloat162 t = __floats2bfloat162_rn(x, y);
    return *(uint32_t*)&t;
}

__global__ void __launch_bounds__(256) k_gemm_mma(
    const float* __restrict__ A,
    const __nv_bfloat16* __restrict__ Bh, const __nv_bfloat16* __restrict__ Bl,
    float* __restrict__ C, int M,
    const float* __restrict__ bn_sum, const float* __restrict__ bn_sumsq,
    const float* __restrict__ gamma, const float* __restrict__ beta,
    const float* __restrict__ alpha_p, int applyBN)
{
    extern __shared__ char sm[];
    int tid = threadIdx.x, wid = tid >> 5, lane = tid & 31;

    // --- load W tiles (pre-split bf16 [n][k]) ---
    {
        int n = tid >> 1;
        int k0 = (tid & 1) * 64;
        const uint4* bh = (const uint4*)(Bh + (size_t)n * 128 + k0);
        const uint4* bl = (const uint4*)(Bl + (size_t)n * 128 + k0);
        char* wh = sm + SM_WH + n * TROW + k0 * 2;
        char* wl = sm + SM_WL + n * TROW + k0 * 2;
        #pragma unroll
        for (int i = 0; i < 8; ++i) {
            *(uint4*)(wh + i * 16) = bh[i];
            *(uint4*)(wl + i * 16) = bl[i];
        }
    }
    // --- load A rows (f32), fused BN+PReLU, split to bf16 hi/lo in smem ---
    {
        int r = tid >> 1;
        int k0 = (tid & 1) * 64;
        int gr = blockIdx.x * 128 + r;
        bool valid = gr < M;
        float alpha = applyBN ? *alpha_p : 0.f;
        const float invN = 1.0f / (float)NN;
        char* ah = sm + SM_AH + r * TROW + k0 * 2;
        char* al = sm + SM_AL + r * TROW + k0 * 2;
        #pragma unroll
        for (int i = 0; i < 16; ++i) {
            int k = k0 + i * 4;
            float v[4] = {0.f, 0.f, 0.f, 0.f};
            if (valid) {
                float4 f = *(const float4*)(A + (size_t)gr * 128 + k);
                v[0] = f.x; v[1] = f.y; v[2] = f.z; v[3] = f.w;
            }
            if (applyBN) {
                #pragma unroll
                for (int j = 0; j < 4; ++j) {
                    int kk = k + j;
                    float mu  = bn_sum[kk] * invN;
                    float var = bn_sumsq[kk] * invN - mu * mu;
                    float rs  = rsqrtf(var + BN_EPS);
                    float z = (v[j] - mu) * rs * gamma[kk] + beta[kk];
                    v[j] = (z > 0.f) ? z : alpha * z;
                }
            }
            uint32_t h0 = pack_bf2(v[0], v[1]), h1 = pack_bf2(v[2], v[3]);
            float r0 = v[0] - __bfloat162float(__ushort_as_bfloat16((unsigned short)(h0 & 0xFFFF)));
            float r1 = v[1] - __bfloat162float(__ushort_as_bfloat16((unsigned short)(h0 >> 16)));
            float r2 = v[2] - __bfloat162float(__ushort_as_bfloat16((unsigned short)(h1 & 0xFFFF)));
            float r3 = v[3] - __bfloat162float(__ushort_as_bfloat16((unsigned short)(h1 >> 16)));
            uint32_t l0 = pack_bf2(r0, r1), l1 = pack_bf2(r2, r3);
            *(uint2*)(ah + i * 8) = make_uint2(h0, h1);
            *(uint2*)(al + i * 8) = make_uint2(l0, l1);
        }
    }
    __syncthreads();

    // --- warp-level MMA: warp wid owns rows [wid*16, wid*16+16), all 128 cols ---
    float acc[16][4];
    #pragma unroll
    for (int t = 0; t < 16; ++t)
        #pragma unroll
        for (int q = 0; q < 4; ++q) acc[t][q] = 0.f;

    int qrow = lane >> 2;              // 0..7
    int kb   = (lane & 3) * 4;         // byte offset of k pair within k-step

    #pragma unroll
    for (int kk = 0; kk < 8; ++kk) {
        int kbyte = kk * 32 + kb;
        const char* arow0 = sm + SM_AH + (wid * 16 + qrow) * TROW + kbyte;
        const char* arow0l = sm + SM_AL + (wid * 16 + qrow) * TROW + kbyte;
        uint32_t a_h[4], a_l[4];
        a_h[0] = *(const uint32_t*)(arow0);
        a_h[1] = *(const uint32_t*)(arow0 + 8 * TROW);
        a_h[2] = *(const uint32_t*)(arow0 + 16);
        a_h[3] = *(const uint32_t*)(arow0 + 8 * TROW + 16);
        a_l[0] = *(const uint32_t*)(arow0l);
        a_l[1] = *(const uint32_t*)(arow0l + 8 * TROW);
        a_l[2] = *(const uint32_t*)(arow0l + 16);
        a_l[3] = *(const uint32_t*)(arow0l + 8 * TROW + 16);
        #pragma unroll
        for (int nt = 0; nt < 16; ++nt) {
            const char* brow = sm + SM_WH + (nt * 8 + qrow) * TROW + kbyte;
            const char* browl = sm + SM_WL + (nt * 8 + qrow) * TROW + kbyte;
            uint32_t b_h[2], b_l[2];
            b_h[0] = *(const uint32_t*)(brow);
            b_h[1] = *(const uint32_t*)(brow + 16);
            b_l[0] = *(const uint32_t*)(browl);
            b_l[1] = *(const uint32_t*)(browl + 16);
            mma_bf16(acc[nt], a_h, b_h);
            mma_bf16(acc[nt], a_h, b_l);
            mma_bf16(acc[nt], a_l, b_h);
        }
    }

    // --- epilogue: store to global ---
    int row0 = blockIdx.x * 128 + wid * 16 + qrow;
    int row1 = row0 + 8;
    int colb = (lane & 3) * 2;
    #pragma unroll
    for (int nt = 0; nt < 16; ++nt) {
        int col = nt * 8 + colb;
        if (row0 < M) *(float2*)(C + (size_t)row0 * 128 + col) = make_float2(acc[nt][0], acc[nt][1]);
        if (row1 < M) *(float2*)(C + (size_t)row1 * 128 + col) = make_float2(acc[nt][2], acc[nt][3]);
    }
}

// ---------------- BatchNorm statistics ----------------
__global__ void k_zero_stats(float* sum, float* sumsq) {
    int t = threadIdx.x;
    if (t < DD) { sum[t] = 0.f; sumsq[t] = 0.f; }
}
__global__ void k_bn_stats(const float* __restrict__ z,
                           float* __restrict__ sum, float* __restrict__ sumsq) {
    int c = threadIdx.x;
    int r0 = blockIdx.x * 128;
    int r1 = min(r0 + 128, NN);
    float s = 0.f, s2 = 0.f;
    for (int r = r0; r < r1; ++r) {
        float v = z[(size_t)r * DD + c];
        s += v; s2 += v * v;
    }
    atomicAdd(&sum[c], s);
    atomicAdd(&sumsq[c], s2);
}

// BN apply + PReLU + mixture accumulate into output
__global__ void k_bn_prelu_mix(const float* __restrict__ t,
                               const float* __restrict__ sum, const float* __restrict__ sumsq,
                               const float* __restrict__ gamma, const float* __restrict__ beta,
                               const float* __restrict__ alpha_p,
                               const float* __restrict__ mix, int g,
                               float* __restrict__ out, int first) {
    int idx = blockIdx.x * blockDim.x + threadIdx.x;
    if (idx >= NN * DD) return;
    int c = idx & 127;
    const float invN = 1.0f / (float)NN;
    float mu  = sum[c] * invN;
    float var = sumsq[c] * invN - mu * mu;
    float rs  = rsqrtf(var + BN_EPS);
    float v   = (t[idx] - mu) * rs * gamma[c] + beta[c];
    float a   = *alpha_p;
    v = (v > 0.f) ? v : a * v;
    float m = mix[(size_t)(idx >> 7) * GG + g];
    if (first) out[idx] = m * v;
    else       out[idx] += m * v;
}

// ---------------- launch ----------------
extern "C" void kernel_launch(void* const* d_in, const int* in_sizes, int n_in,
                              void* d_out, int out_size) {
    const float* x      = (const float*)d_in[0];
    const int*   ei     = (const int*)d_in[1];
    const float* W1     = (const float*)d_in[2];
    const float* W2     = (const float*)d_in[4];
    const float* gamma1 = (const float*)d_in[6];
    const float* beta1  = (const float*)d_in[7];
    const float* gamma2 = (const float*)d_in[8];
    const float* beta2  = (const float*)d_in[9];
    const float* alpha  = (const float*)d_in[10];
    const float* mixe   = (const float*)d_in[11];
    float*       out    = (float*)d_out;

    void* p;
    cudaGetSymbolAddress(&p, g_cnt);    int* cnt    = (int*)p;
    cudaGetSymbolAddress(&p, g_rowptr); int* rowptr = (int*)p;
    cudaGetSymbolAddress(&p, g_cursor); int* cursor = (int*)p;
    cudaGetSymbolAddress(&p, g_bsum);   int* bsum   = (int*)p;
    cudaGetSymbolAddress(&p, g_esrc);   int* esrc   = (int*)p;
    cudaGetSymbolAddress(&p, g_enorm);  float* enorm= (float*)p;
    cudaGetSymbolAddress(&p, g_dinv);   float* dinv = (float*)p;
    cudaGetSymbolAddress(&p, g_xa);     float* xa   = (float*)p;
    cudaGetSymbolAddress(&p, g_z1);     float* z1   = (float*)p;
    cudaGetSymbolAddress(&p, g_h2);     float* h2   = (float*)p;
    cudaGetSymbolAddress(&p, g_t2);     float* t2   = (float*)p;
    cudaGetSymbolAddress(&p, g_mix);    float* mix  = (float*)p;
    cudaGetSymbolAddress(&p, g_sum);    float* sum  = (float*)p;
    cudaGetSymbolAddress(&p, g_sumsq);  float* sumsq= (float*)p;
    cudaGetSymbolAddress(&p, g_w1h);    __nv_bfloat16* w1h = (__nv_bfloat16*)p;
    cudaGetSymbolAddress(&p, g_w1l);    __nv_bfloat16* w1l = (__nv_bfloat16*)p;
    cudaGetSymbolAddress(&p, g_w2h);    __nv_bfloat16* w2h = (__nv_bfloat16*)p;
    cudaGetSymbolAddress(&p, g_w2l);    __nv_bfloat16* w2l = (__nv_bfloat16*)p;

    const int* row = ei;
    const int* col = ei + EE;

    const int T = 256;
    const int gN    = (NN + T) / T;
    const int gE    = (EE + T - 1) / T;
    const int gND   = (NN * DD + T - 1) / T;
    const int gRow  = (NN + 127) / 128;          // 391
    const int gW    = (GG * DD * DD + T - 1) / T;
    const int nScan = (NN + 1 + 511) / 512;      // 98
    const int gGath = (NN + 7) / 8;              // 6250

    cudaFuncSetAttribute(k_gemm_mma, cudaFuncAttributeMaxDynamicSharedMemorySize, GT_SMEM);

    // graph CSR + normalization (recomputed per call; deterministic within tolerance)
    k_zero_cnt<<<gN, T>>>(cnt);
    k_hist<<<gE, T>>>(col, cnt);
    k_dinv<<<gN, T>>>(cnt, dinv);
    k_scan1<<<nScan, 512>>>(cnt, rowptr, bsum);
    k_scan2<<<1, 128>>>(bsum, nScan);
    k_scan3<<<nScan, 512>>>(rowptr, bsum, cursor);
    k_place<<<gE, T>>>(row, col, dinv, cursor, esrc, enorm);
    k_mix_softmax<<<gN, T>>>(mixe, mix);
    k_split_w<<<gW, T>>>(W1, w1h, w1l);
    k_split_w<<<gW, T>>>(W2, w2h, w2l);

    // shared layer-1 propagate: xa = P @ x  (self-loop fused)
    k_gather<<<gGath, T>>>((const float4*)x, (float4*)xa, rowptr, esrc, enorm, dinv);

    for (int g = 0; g < GG; ++g) {
        const size_t wofs = (size_t)g * DD * DD;
        // layer 1: z1(pre-BN) = (P x) @ W1[g]   (b1 cancels in BN)
        k_gemm_mma<<<gRow, T, GT_SMEM>>>(xa, w1h + wofs, w1l + wofs, z1, NN,
                                         nullptr, nullptr, nullptr, nullptr, nullptr, 0);
        k_zero_stats<<<1, 128>>>(sum, sumsq);
        k_bn_stats<<<gRow, 128>>>(z1, sum, sumsq);

        // layer 2: h2 = prelu(BN(z1)) @ W2[g]  (BN+PReLU fused into A-load)
        k_gemm_mma<<<gRow, T, GT_SMEM>>>(z1, w2h + wofs, w2l + wofs, h2, NN,
                                         sum, sumsq, gamma1 + g * DD, beta1 + g * DD, alpha, 1);
        k_gather<<<gGath, T>>>((const float4*)h2, (float4*)t2, rowptr, esrc, enorm, dinv);
        k_zero_stats<<<1, 128>>>(sum, sumsq);
        k_bn_stats<<<gRow, 128>>>(t2, sum, sumsq);
        k_bn_prelu_mix<<<gND, T>>>(t2, sum, sumsq, gamma2 + g * DD, beta2 + g * DD,
                                   alpha, mix, g, out, g == 0 ? 1 : 0);
    }
}

// round 5
// speedup vs baseline: 2.4917x; 1.2025x over previous
#include <cuda_runtime.h>
#include <cuda_bf16.h>
#include <cstdint>
#include <cstddef>

#define NN 50000
#define EE 800000
#define DD 128
#define GG 4
#define BN_EPS 1e-5f

// ---------------- static scratch (no allocations allowed) ----------------
__device__ int   g_cnt[NN + 1];
__device__ int   g_rowptr[NN + 1];
__device__ int   g_cursor[NN];
__device__ int   g_bsum[128];
__device__ int   g_esrc[EE];
__device__ float g_enorm[EE];
__device__ float g_dinv[NN];
__device__ float g_xa[(size_t)NN * DD];
__device__ float g_z1[(size_t)GG * NN * DD];
__device__ float g_h2[(size_t)GG * NN * DD];
__device__ float g_t2[(size_t)GG * NN * DD];
__device__ float g_mix[(size_t)NN * GG];
__device__ float g_s1[GG * DD];
__device__ float g_q1[GG * DD];
__device__ float g_s2[GG * DD];
__device__ float g_q2[GG * DD];
__device__ __nv_bfloat16 g_w1h[(size_t)GG * DD * DD];
__device__ __nv_bfloat16 g_w1l[(size_t)GG * DD * DD];
__device__ __nv_bfloat16 g_w2h[(size_t)GG * DD * DD];
__device__ __nv_bfloat16 g_w2l[(size_t)GG * DD * DD];

// ---------------- setup: degree, CSR build, softmax, weight split ----------------
__global__ void k_zero_cnt(int* cnt) {
    int i = blockIdx.x * blockDim.x + threadIdx.x;
    if (i <= NN) cnt[i] = 0;
}
__global__ void k_hist(const int* __restrict__ col, int* cnt) {
    int e = blockIdx.x * blockDim.x + threadIdx.x;
    if (e >= EE) return;
    int c = col[e];
    if ((unsigned)c < (unsigned)NN) atomicAdd(&cnt[c], 1);
}
__global__ void k_dinv(const int* __restrict__ cnt, float* dinv) {
    int i = blockIdx.x * blockDim.x + threadIdx.x;
    if (i < NN) dinv[i] = rsqrtf((float)cnt[i] + 1.0f);  // +1 self-loop
}
__global__ void k_scan1(const int* __restrict__ cnt, int* __restrict__ rowptr, int* __restrict__ bsum) {
    __shared__ int s[512];
    int tid = threadIdx.x;
    int i = blockIdx.x * 512 + tid;
    int v = (i <= NN) ? cnt[i] : 0;
    s[tid] = v;
    __syncthreads();
    #pragma unroll
    for (int off = 1; off < 512; off <<= 1) {
        int t = (tid >= off) ? s[tid - off] : 0;
        __syncthreads();
        s[tid] += t;
        __syncthreads();
    }
    if (i <= NN) rowptr[i] = s[tid] - v;
    if (tid == 511) bsum[blockIdx.x] = s[511];
}
__global__ void k_scan2(int* bsum, int nb) {
    __shared__ int s[128];
    int tid = threadIdx.x;
    int v = (tid < nb) ? bsum[tid] : 0;
    s[tid] = v;
    __syncthreads();
    #pragma unroll
    for (int off = 1; off < 128; off <<= 1) {
        int t = (tid >= off) ? s[tid - off] : 0;
        __syncthreads();
        s[tid] += t;
        __syncthreads();
    }
    if (tid < nb) bsum[tid] = s[tid] - v;
}
__global__ void k_scan3(int* __restrict__ rowptr, const int* __restrict__ bsum, int* __restrict__ cursor) {
    int i = blockIdx.x * 512 + threadIdx.x;
    if (i <= NN) {
        int r = rowptr[i] + bsum[blockIdx.x];
        rowptr[i] = r;
        if (i < NN) cursor[i] = r;
    }
}
__global__ void k_place(const int* __restrict__ row, const int* __restrict__ col,
                        const float* __restrict__ dinv,
                        int* __restrict__ cursor, int* __restrict__ esrc, float* __restrict__ enorm) {
    int e = blockIdx.x * blockDim.x + threadIdx.x;
    if (e >= EE) return;
    int r = row[e], c = col[e];
    if ((unsigned)r >= (unsigned)NN || (unsigned)c >= (unsigned)NN) return;
    int pos = atomicAdd(&cursor[c], 1);
    esrc[pos] = r;
    enorm[pos] = dinv[r] * dinv[c];
}
__global__ void k_mix_softmax(const float* __restrict__ me, float* __restrict__ mix) {
    int n = blockIdx.x * blockDim.x + threadIdx.x;
    if (n >= NN) return;
    float m0 = me[n*4+0], m1 = me[n*4+1], m2 = me[n*4+2], m3 = me[n*4+3];
    float mx = fmaxf(fmaxf(m0, m1), fmaxf(m2, m3));
    float e0 = expf(m0-mx), e1 = expf(m1-mx), e2 = expf(m2-mx), e3 = expf(m3-mx);
    float inv = 1.0f / (e0 + e1 + e2 + e3);
    mix[n*4+0] = e0*inv; mix[n*4+1] = e1*inv; mix[n*4+2] = e2*inv; mix[n*4+3] = e3*inv;
}
__global__ void k_split_w(const float* __restrict__ W,
                          __nv_bfloat16* __restrict__ Wh, __nv_bfloat16* __restrict__ Wl) {
    int idx = blockIdx.x * blockDim.x + threadIdx.x;
    if (idx >= GG * DD * DD) return;
    int g = idx >> 14, rem = idx & 16383, n = rem >> 7, k = rem & 127;
    float w = W[(g << 14) + (k << 7) + n];
    __nv_bfloat16 h = __float2bfloat16(w);
    Wh[idx] = h;
    Wl[idx] = __float2bfloat16(w - __bfloat162float(h));
}
__global__ void k_zero_stats4(float* s1, float* q1, float* s2, float* q2) {
    int t = threadIdx.x;   // 512 threads == GG*DD
    s1[t] = 0.f; q1[t] = 0.f; s2[t] = 0.f; q2[t] = 0.f;
}

// ---------------- propagate: CSR gather, warp handles 8 nodes, fused BN stats ----------------
__global__ void __launch_bounds__(256) k_gather(
    const float4* __restrict__ src, float4* __restrict__ dst,
    const int* __restrict__ rowptr, const int* __restrict__ esrc,
    const float* __restrict__ enorm, const float* __restrict__ dinv,
    float* osum, float* osumsq, int wantStats, size_t srcStride4)
{
    __shared__ float sbs[128], sbq[128];
    int gy = blockIdx.y;
    src += (size_t)gy * srcStride4;
    dst += (size_t)gy * NN * 32;
    int tid = threadIdx.x, wid = tid >> 5, lane = tid & 31;
    if (wantStats) {
        if (tid < 128) { sbs[tid] = 0.f; sbq[tid] = 0.f; }
        __syncthreads();
    }
    float s[4] = {0.f, 0.f, 0.f, 0.f}, q[4] = {0.f, 0.f, 0.f, 0.f};
    int n0 = blockIdx.x * 64 + wid * 8;
    for (int i = 0; i < 8; ++i) {
        int n = n0 + i;
        if (n >= NN) break;
        float dw = dinv[n];
        float w0 = dw * dw;
        float4 a = src[(size_t)n * 32 + lane];
        float4 acc = make_float4(a.x * w0, a.y * w0, a.z * w0, a.w * w0);
        int j0 = rowptr[n], j1 = rowptr[n + 1];
        for (int j = j0; j < j1; ++j) {
            int sn = esrc[j];
            float w = enorm[j];
            float4 v = src[(size_t)sn * 32 + lane];
            acc.x += w * v.x; acc.y += w * v.y; acc.z += w * v.z; acc.w += w * v.w;
        }
        dst[(size_t)n * 32 + lane] = acc;
        if (wantStats) {
            s[0] += acc.x; q[0] += acc.x * acc.x;
            s[1] += acc.y; q[1] += acc.y * acc.y;
            s[2] += acc.z; q[2] += acc.z * acc.z;
            s[3] += acc.w; q[3] += acc.w * acc.w;
        }
    }
    if (wantStats) {
        int c = lane * 4;
        atomicAdd(&sbs[c + 0], s[0]); atomicAdd(&sbq[c + 0], q[0]);
        atomicAdd(&sbs[c + 1], s[1]); atomicAdd(&sbq[c + 1], q[1]);
        atomicAdd(&sbs[c + 2], s[2]); atomicAdd(&sbq[c + 2], q[2]);
        atomicAdd(&sbs[c + 3], s[3]); atomicAdd(&sbq[c + 3], q[3]);
        __syncthreads();
        if (tid < 128) {
            atomicAdd(&osum[gy * DD + tid], sbs[tid]);
            atomicAdd(&osumsq[gy * DD + tid], sbq[tid]);
        }
    }
}

// ---------------- GEMM: C = A @ W^T, mma.sync bf16 3-term split, fused BN in/out ----------------
#define TROW 272
#define SM_WH 0
#define SM_WL (SM_WH + 128 * TROW)
#define SM_AH (SM_WL + 128 * TROW)
#define SM_AL (SM_AH + 128 * TROW)
#define GT_SMEM (SM_AL + 128 * TROW)

__device__ __forceinline__ void mma_bf16(float* d, const uint32_t* a, const uint32_t* b) {
    asm volatile(
        "mma.sync.aligned.m16n8k16.row.col.f32.bf16.bf16.f32 "
        "{%0,%1,%2,%3}, {%4,%5,%6,%7}, {%8,%9}, {%0,%1,%2,%3};"
        : "+f"(d[0]), "+f"(d[1]), "+f"(d[2]), "+f"(d[3])
        : "r"(a[0]), "r"(a[1]), "r"(a[2]), "r"(a[3]), "r"(b[0]), "r"(b[1]));
}
__device__ __forceinline__ uint32_t pack_bf2(float x, float y) {
    __nv_bfloat162 t = __floats2bfloat162_rn(x, y);
    return *(uint32_t*)&t;
}

__global__ void __launch_bounds__(256) k_gemm_mma(
    const float* __restrict__ A,
    const __nv_bfloat16* __restrict__ Bh, const __nv_bfloat16* __restrict__ Bl,
    float* __restrict__ C, int M,
    const float* __restrict__ bn_sum, const float* __restrict__ bn_sumsq,
    const float* __restrict__ gamma, const float* __restrict__ beta,
    const float* __restrict__ alpha_p, int applyBN,
    float* osum, float* osumsq, int wantStats, size_t aStride)
{
    extern __shared__ char sm[];
    __shared__ float sbs[128], sbq[128];
    int gy = blockIdx.y;
    A  += (size_t)gy * aStride;
    Bh += (size_t)gy * (DD * DD);
    Bl += (size_t)gy * (DD * DD);
    C  += (size_t)gy * NN * DD;
    if (applyBN) {
        bn_sum += gy * DD; bn_sumsq += gy * DD;
        gamma  += gy * DD; beta     += gy * DD;
    }
    int tid = threadIdx.x, wid = tid >> 5, lane = tid & 31;

    if (wantStats && tid < 128) { sbs[tid] = 0.f; sbq[tid] = 0.f; }

    // --- load W tiles (pre-split bf16 [n][k]) ---
    {
        int n = tid >> 1;
        int k0 = (tid & 1) * 64;
        const uint4* bh = (const uint4*)(Bh + (size_t)n * 128 + k0);
        const uint4* bl = (const uint4*)(Bl + (size_t)n * 128 + k0);
        char* wh = sm + SM_WH + n * TROW + k0 * 2;
        char* wl = sm + SM_WL + n * TROW + k0 * 2;
        #pragma unroll
        for (int i = 0; i < 8; ++i) {
            *(uint4*)(wh + i * 16) = bh[i];
            *(uint4*)(wl + i * 16) = bl[i];
        }
    }
    // --- load A rows (f32), fused BN+PReLU, split to bf16 hi/lo in smem ---
    {
        int r = tid >> 1;
        int k0 = (tid & 1) * 64;
        int gr = blockIdx.x * 128 + r;
        bool valid = gr < M;
        float alpha = applyBN ? *alpha_p : 0.f;
        const float invN = 1.0f / (float)NN;
        char* ah = sm + SM_AH + r * TROW + k0 * 2;
        char* al = sm + SM_AL + r * TROW + k0 * 2;
        #pragma unroll
        for (int i = 0; i < 16; ++i) {
            int k = k0 + i * 4;
            float v[4] = {0.f, 0.f, 0.f, 0.f};
            if (valid) {
                float4 f = *(const float4*)(A + (size_t)gr * 128 + k);
                v[0] = f.x; v[1] = f.y; v[2] = f.z; v[3] = f.w;
            }
            if (applyBN) {
                #pragma unroll
                for (int j = 0; j < 4; ++j) {
                    int kk = k + j;
                    float mu  = bn_sum[kk] * invN;
                    float var = bn_sumsq[kk] * invN - mu * mu;
                    float rs  = rsqrtf(var + BN_EPS);
                    float z = (v[j] - mu) * rs * gamma[kk] + beta[kk];
                    v[j] = (z > 0.f) ? z : alpha * z;
                }
            }
            uint32_t h0 = pack_bf2(v[0], v[1]), h1 = pack_bf2(v[2], v[3]);
            float r0 = v[0] - __bfloat162float(__ushort_as_bfloat16((unsigned short)(h0 & 0xFFFF)));
            float r1 = v[1] - __bfloat162float(__ushort_as_bfloat16((unsigned short)(h0 >> 16)));
            float r2 = v[2] - __bfloat162float(__ushort_as_bfloat16((unsigned short)(h1 & 0xFFFF)));
            float r3 = v[3] - __bfloat162float(__ushort_as_bfloat16((unsigned short)(h1 >> 16)));
            uint32_t l0 = pack_bf2(r0, r1), l1 = pack_bf2(r2, r3);
            *(uint2*)(ah + i * 8) = make_uint2(h0, h1);
            *(uint2*)(al + i * 8) = make_uint2(l0, l1);
        }
    }
    __syncthreads();

    // --- warp-level MMA: warp wid owns rows [wid*16, wid*16+16), all 128 cols ---
    float acc[16][4];
    #pragma unroll
    for (int t = 0; t < 16; ++t)
        #pragma unroll
        for (int qq = 0; qq < 4; ++qq) acc[t][qq] = 0.f;

    int qrow = lane >> 2;
    int kb   = (lane & 3) * 4;

    #pragma unroll
    for (int kk = 0; kk < 8; ++kk) {
        int kbyte = kk * 32 + kb;
        const char* arow0  = sm + SM_AH + (wid * 16 + qrow) * TROW + kbyte;
        const char* arow0l = sm + SM_AL + (wid * 16 + qrow) * TROW + kbyte;
        uint32_t a_h[4], a_l[4];
        a_h[0] = *(const uint32_t*)(arow0);
        a_h[1] = *(const uint32_t*)(arow0 + 8 * TROW);
        a_h[2] = *(const uint32_t*)(arow0 + 16);
        a_h[3] = *(const uint32_t*)(arow0 + 8 * TROW + 16);
        a_l[0] = *(const uint32_t*)(arow0l);
        a_l[1] = *(const uint32_t*)(arow0l + 8 * TROW);
        a_l[2] = *(const uint32_t*)(arow0l + 16);
        a_l[3] = *(const uint32_t*)(arow0l + 8 * TROW + 16);
        #pragma unroll
        for (int nt = 0; nt < 16; ++nt) {
            const char* brow  = sm + SM_WH + (nt * 8 + qrow) * TROW + kbyte;
            const char* browl = sm + SM_WL + (nt * 8 + qrow) * TROW + kbyte;
            uint32_t b_h[2], b_l[2];
            b_h[0] = *(const uint32_t*)(brow);
            b_h[1] = *(const uint32_t*)(brow + 16);
            b_l[0] = *(const uint32_t*)(browl);
            b_l[1] = *(const uint32_t*)(browl + 16);
            mma_bf16(acc[nt], a_h, b_h);
            mma_bf16(acc[nt], a_h, b_l);
            mma_bf16(acc[nt], a_l, b_h);
        }
    }

    // --- epilogue: store to global + optional fused BN stats ---
    int row0 = blockIdx.x * 128 + wid * 16 + qrow;
    int row1 = row0 + 8;
    int colb = (lane & 3) * 2;
    #pragma unroll
    for (int nt = 0; nt < 16; ++nt) {
        int col = nt * 8 + colb;
        if (row0 < M) *(float2*)(C + (size_t)row0 * 128 + col) = make_float2(acc[nt][0], acc[nt][1]);
        if (row1 < M) *(float2*)(C + (size_t)row1 * 128 + col) = make_float2(acc[nt][2], acc[nt][3]);
    }
    if (wantStats) {
        // invalid tail rows contribute exact zeros (A tile zero-filled) — safe to include
        #pragma unroll
        for (int nt = 0; nt < 16; ++nt) {
            float s0 = acc[nt][0] + acc[nt][2];
            float s1 = acc[nt][1] + acc[nt][3];
            float q0 = acc[nt][0]*acc[nt][0] + acc[nt][2]*acc[nt][2];
            float q1 = acc[nt][1]*acc[nt][1] + acc[nt][3]*acc[nt][3];
            #pragma unroll
            for (int o = 4; o < 32; o <<= 1) {
                s0 += __shfl_xor_sync(0xffffffffu, s0, o);
                s1 += __shfl_xor_sync(0xffffffffu, s1, o);
                q0 += __shfl_xor_sync(0xffffffffu, q0, o);
                q1 += __shfl_xor_sync(0xffffffffu, q1, o);
            }
            if (lane < 4) {
                int c0 = nt * 8 + lane * 2;
                atomicAdd(&sbs[c0],     s0); atomicAdd(&sbq[c0],     q0);
                atomicAdd(&sbs[c0 + 1], s1); atomicAdd(&sbq[c0 + 1], q1);
            }
        }
        __syncthreads();
        if (tid < 128) {
            atomicAdd(&osum[gy * DD + tid], sbs[tid]);
            atomicAdd(&osumsq[gy * DD + tid], sbq[tid]);
        }
    }
}

// ---------------- final: BN2 + PReLU + mixture over all G, single pass ----------------
__global__ void k_final(const float* __restrict__ t2,
                        const float* __restrict__ s2, const float* __restrict__ q2,
                        const float* __restrict__ gamma2, const float* __restrict__ beta2,
                        const float* __restrict__ alpha_p,
                        const float* __restrict__ mix, float* __restrict__ out) {
    int idx = blockIdx.x * blockDim.x + threadIdx.x;
    if (idx >= NN * DD) return;
    int n = idx >> 7, c = idx & 127;
    float a = *alpha_p;
    const float invN = 1.0f / (float)NN;
    float r = 0.f;
    #pragma unroll
    for (int g = 0; g < GG; ++g) {
        float mu  = s2[g * DD + c] * invN;
        float var = q2[g * DD + c] * invN - mu * mu;
        float rs  = rsqrtf(var + BN_EPS);
        float v = (t2[(size_t)g * NN * DD + idx] - mu) * rs * gamma2[g * DD + c] + beta2[g * DD + c];
        v = (v > 0.f) ? v : a * v;
        r += mix[(size_t)n * GG + g] * v;
    }
    out[idx] = r;
}

// ---------------- launch ----------------
extern "C" void kernel_launch(void* const* d_in, const int* in_sizes, int n_in,
                              void* d_out, int out_size) {
    const float* x      = (const float*)d_in[0];
    const int*   ei     = (const int*)d_in[1];
    const float* W1     = (const float*)d_in[2];
    const float* W2     = (const float*)d_in[4];
    const float* gamma1 = (const float*)d_in[6];
    const float* gamma2 = (const float*)d_in[8];
    const float* beta1  = (const float*)d_in[7];
    const float* beta2  = (const float*)d_in[9];
    const float* alpha  = (const float*)d_in[10];
    const float* mixe   = (const float*)d_in[11];
    float*       out    = (float*)d_out;

    void* p;
    cudaGetSymbolAddress(&p, g_cnt);    int* cnt    = (int*)p;
    cudaGetSymbolAddress(&p, g_rowptr); int* rowptr = (int*)p;
    cudaGetSymbolAddress(&p, g_cursor); int* cursor = (int*)p;
    cudaGetSymbolAddress(&p, g_bsum);   int* bsum   = (int*)p;
    cudaGetSymbolAddress(&p, g_esrc);   int* esrc   = (int*)p;
    cudaGetSymbolAddress(&p, g_enorm);  float* enorm= (float*)p;
    cudaGetSymbolAddress(&p, g_dinv);   float* dinv = (float*)p;
    cudaGetSymbolAddress(&p, g_xa);     float* xa   = (float*)p;
    cudaGetSymbolAddress(&p, g_z1);     float* z1   = (float*)p;
    cudaGetSymbolAddress(&p, g_h2);     float* h2   = (float*)p;
    cudaGetSymbolAddress(&p, g_t2);     float* t2   = (float*)p;
    cudaGetSymbolAddress(&p, g_mix);    float* mix  = (float*)p;
    cudaGetSymbolAddress(&p, g_s1);     float* s1   = (float*)p;
    cudaGetSymbolAddress(&p, g_q1);     float* q1   = (float*)p;
    cudaGetSymbolAddress(&p, g_s2);     float* s2   = (float*)p;
    cudaGetSymbolAddress(&p, g_q2);     float* q2   = (float*)p;
    cudaGetSymbolAddress(&p, g_w1h);    __nv_bfloat16* w1h = (__nv_bfloat16*)p;
    cudaGetSymbolAddress(&p, g_w1l);    __nv_bfloat16* w1l = (__nv_bfloat16*)p;
    cudaGetSymbolAddress(&p, g_w2h);    __nv_bfloat16* w2h = (__nv_bfloat16*)p;
    cudaGetSymbolAddress(&p, g_w2l);    __nv_bfloat16* w2l = (__nv_bfloat16*)p;

    const int* row = ei;
    const int* col = ei + EE;

    const int T = 256;
    const int gN    = (NN + T) / T;
    const int gE    = (EE + T - 1) / T;
    const int gND   = (NN * DD + T - 1) / T;
    const int gRow  = (NN + 127) / 128;          // 391
    const int gW    = (GG * DD * DD + T - 1) / T;
    const int nScan = (NN + 1 + 511) / 512;      // 98
    const int gGath = (NN + 63) / 64;            // 782

    cudaFuncSetAttribute(k_gemm_mma, cudaFuncAttributeMaxDynamicSharedMemorySize, GT_SMEM);

    // graph CSR + normalization + weight split (recomputed per call)
    k_zero_cnt<<<gN, T>>>(cnt);
    k_hist<<<gE, T>>>(col, cnt);
    k_dinv<<<gN, T>>>(cnt, dinv);
    k_scan1<<<nScan, 512>>>(cnt, rowptr, bsum);
    k_scan2<<<1, 128>>>(bsum, nScan);
    k_scan3<<<nScan, 512>>>(rowptr, bsum, cursor);
    k_place<<<gE, T>>>(row, col, dinv, cursor, esrc, enorm);
    k_mix_softmax<<<gN, T>>>(mixe, mix);
    k_split_w<<<gW, T>>>(W1, w1h, w1l);
    k_split_w<<<gW, T>>>(W2, w2h, w2l);
    k_zero_stats4<<<1, GG * DD>>>(s1, q1, s2, q2);

    // shared layer-1 propagate: xa = P @ x
    k_gather<<<dim3(gGath, 1), T>>>((const float4*)x, (float4*)xa,
                                    rowptr, esrc, enorm, dinv, nullptr, nullptr, 0, 0);

    // layer 1 (all G): z1[g] = xa @ W1[g]^T, fused stats -> s1/q1
    k_gemm_mma<<<dim3(gRow, GG), T, GT_SMEM>>>(
        xa, w1h, w1l, z1, NN,
        nullptr, nullptr, nullptr, nullptr, nullptr, 0,
        s1, q1, 1, 0 /* shared A */);

    // layer 2 (all G): h2[g] = prelu(BN(z1[g])) @ W2[g]^T, BN fused in A-load
    k_gemm_mma<<<dim3(gRow, GG), T, GT_SMEM>>>(
        z1, w2h, w2l, h2, NN,
        s1, q1, gamma1, beta1, alpha, 1,
        nullptr, nullptr, 0, (size_t)NN * DD);

    // propagate (all G): t2[g] = P @ h2[g], fused stats -> s2/q2
    k_gather<<<dim3(gGath, GG), T>>>((const float4*)h2, (float4*)t2,
                                     rowptr, esrc, enorm, dinv, s2, q2, 1, (size_t)NN * 32);

    // final: BN2 + PReLU + softmax-mix accumulate, single pass
    k_final<<<gND, T>>>(t2, s2, q2, gamma2, beta2, alpha, mix, out);
}